// round 3
// baseline (speedup 1.0000x reference)
#include <cuda_runtime.h>
#include <math.h>

#define N_NODES_MAX 100000
#define E_MAX       1600000
#define D1 64
#define D2 32

// Scratch (no allocations allowed)
__device__ float g_x2t[(size_t)N_NODES_MAX * D2];  // (relu(agg@W1+b1)) @ W2, [N,32]
__device__ int   g_cnt[N_NODES_MAX];               // degree histogram
__device__ int   g_row[N_NODES_MAX + 1];           // CSR row offsets
__device__ int   g_cur[N_NODES_MAX];               // fill cursors
__device__ int   g_csr[E_MAX];                     // CSR src indices (grouped by dst)

// ---------------------------------------------------------------------------
// Degree histogram over edge destinations.
__global__ void hist_kernel(const int* __restrict__ dst, int* __restrict__ cnt, int E) {
    int i = blockIdx.x * blockDim.x + threadIdx.x;
    if (i < E) atomicAdd(&cnt[dst[i]], 1);
}

// ---------------------------------------------------------------------------
// Single-block exclusive scan over cnt[0..N): writes row (exclusive prefix),
// cur (copy of row), and row[N]=E. 1024 threads, sequential chunk per thread.
__global__ void __launch_bounds__(1024)
scan_all_kernel(const int* __restrict__ cnt,
                int* __restrict__ row, int* __restrict__ cur,
                int N, int E) {
    __shared__ int s[1024];
    int t = threadIdx.x;
    int chunk = (N + 1023) / 1024;
    int beg = t * chunk;
    int end = min(beg + chunk, N);

    int local = 0;
    for (int i = beg; i < end; i++) local += cnt[i];
    s[t] = local;
    __syncthreads();
#pragma unroll
    for (int off = 1; off < 1024; off <<= 1) {
        int u = 0;
        if (t >= off) u = s[t - off];
        __syncthreads();
        if (t >= off) s[t] += u;
        __syncthreads();
    }
    int pre = s[t] - local;   // exclusive prefix of this thread's chunk
    for (int i = beg; i < end; i++) {
        row[i] = pre;
        cur[i] = pre;
        pre += cnt[i];
    }
    if (t == 1023) row[N] = E;
}

// ---------------------------------------------------------------------------
// CSR fill: slot each edge's src into its destination's segment.
__global__ void fill_kernel(const int* __restrict__ src, const int* __restrict__ dst,
                            int* __restrict__ cur, int* __restrict__ csr, int E) {
    int i = blockIdx.x * blockDim.x + threadIdx.x;
    if (i < E) {
        int d = dst[i];
        int p = atomicAdd(&cur[d], 1);
        csr[p] = src[i];
    }
}

// ---------------------------------------------------------------------------
// Fused layer 1 + W2 pre-transform:
//   agg = mean(x[neighbors])          (gather, 64 wide)
//   x1  = relu(agg @ W1 + b1)         (64)
//   x2t = x1 @ W2                     (32)  <- stored; aggregation is linear,
//                                              so layer 2 can gather x2t.
// Half-warp (16 lanes) per node.
__global__ void __launch_bounds__(512)
layer1_kernel(const float* __restrict__ x,
              const int*   __restrict__ csr,
              const int*   __restrict__ row,
              const float* __restrict__ W1,   // [64,64] (k, j)
              const float* __restrict__ b1,   // [64]
              const float* __restrict__ W2,   // [64,32] (k, j)
              float*       __restrict__ x2t,  // [N,32]
              int N) {
    __shared__ float W1s[D1 * D1];
    __shared__ float W2s[D1 * D2];
    __shared__ float bs[D1];
    __shared__ float in_s[32][D1];   // 32 half-warps per block

    for (int i = threadIdx.x; i < D1 * D1; i += blockDim.x) W1s[i] = W1[i];
    for (int i = threadIdx.x; i < D1 * D2; i += blockDim.x) W2s[i] = W2[i];
    if (threadIdx.x < D1) bs[threadIdx.x] = b1[threadIdx.x];
    __syncthreads();

    int hw = threadIdx.x >> 4;
    int lane = threadIdx.x & 15;
    int node = blockIdx.x * 32 + hw;
    if (node >= N) node = N - 1;   // duplicates recompute identical values

    int beg = row[node], end = row[node + 1];
    const float4* x4 = reinterpret_cast<const float4*>(x);

    float4 a0 = make_float4(0.f, 0.f, 0.f, 0.f);
    float4 a1 = a0, a2 = a0, a3 = a0;
    int e = beg;
    for (; e + 3 < end; e += 4) {
        int s0 = csr[e], s1 = csr[e + 1], s2 = csr[e + 2], s3 = csr[e + 3];
        float4 v0 = x4[(size_t)s0 * 16 + lane];
        float4 v1 = x4[(size_t)s1 * 16 + lane];
        float4 v2 = x4[(size_t)s2 * 16 + lane];
        float4 v3 = x4[(size_t)s3 * 16 + lane];
        a0.x += v0.x; a0.y += v0.y; a0.z += v0.z; a0.w += v0.w;
        a1.x += v1.x; a1.y += v1.y; a1.z += v1.z; a1.w += v1.w;
        a2.x += v2.x; a2.y += v2.y; a2.z += v2.z; a2.w += v2.w;
        a3.x += v3.x; a3.y += v3.y; a3.z += v3.z; a3.w += v3.w;
    }
    for (; e < end; e++) {
        int s0 = csr[e];
        float4 v0 = x4[(size_t)s0 * 16 + lane];
        a0.x += v0.x; a0.y += v0.y; a0.z += v0.z; a0.w += v0.w;
    }
    float inv = 1.0f / fmaxf((float)(end - beg), 1.0f);
    float4 a;
    a.x = (a0.x + a1.x + a2.x + a3.x) * inv;
    a.y = (a0.y + a1.y + a2.y + a3.y) * inv;
    a.z = (a0.z + a1.z + a2.z + a3.z) * inv;
    a.w = (a0.w + a1.w + a2.w + a3.w) * inv;

    reinterpret_cast<float4*>(&in_s[hw][0])[lane] = a;
    __syncwarp();

    // x1[j..j+3] = relu(agg @ W1 + b1)
    int j = lane * 4;
    float o0 = bs[j + 0], o1 = bs[j + 1], o2 = bs[j + 2], o3 = bs[j + 3];
#pragma unroll
    for (int k = 0; k < D1; k++) {
        float xk = in_s[hw][k];
        float4 w = *reinterpret_cast<const float4*>(&W1s[k * D1 + j]);
        o0 = fmaf(xk, w.x, o0);
        o1 = fmaf(xk, w.y, o1);
        o2 = fmaf(xk, w.z, o2);
        o3 = fmaf(xk, w.w, o3);
    }
    float4 h;
    h.x = fmaxf(o0, 0.f); h.y = fmaxf(o1, 0.f);
    h.z = fmaxf(o2, 0.f); h.w = fmaxf(o3, 0.f);
    __syncwarp();
    reinterpret_cast<float4*>(&in_s[hw][0])[lane] = h;   // in_s now holds x1
    __syncwarp();

    // x2t[j2..j2+1] = x1 @ W2  (no bias/relu here; applied after aggregation)
    int j2 = lane * 2;
    float p0 = 0.f, p1 = 0.f;
#pragma unroll
    for (int k = 0; k < D1; k++) {
        float xk = in_s[hw][k];
        float2 w = *reinterpret_cast<const float2*>(&W2s[k * D2 + j2]);
        p0 = fmaf(xk, w.x, p0);
        p1 = fmaf(xk, w.y, p1);
    }
    reinterpret_cast<float2*>(x2t + (size_t)node * D2)[lane] = make_float2(p0, p1);
}

// ---------------------------------------------------------------------------
// Layer 2 + readout (no GEMM left):
//   agg2 = mean(x2t[neighbors])   (gather, 32 wide)
//   h    = relu(agg2 + b2)
//   out  = sigmoid(mean(h) * Wd + bd)
// 8 lanes per node (each lane owns one float4 = 4 features).
__global__ void __launch_bounds__(512)
layer2_kernel(const float* __restrict__ x2t,  // [N,32]
              const int*   __restrict__ csr,
              const int*   __restrict__ row,
              const float* __restrict__ b2,   // [32]
              const float* __restrict__ Wd,
              const float* __restrict__ bd,
              float*       __restrict__ out,  // [N]
              int N) {
    __shared__ float bs[D2];
    if (threadIdx.x < D2) bs[threadIdx.x] = b2[threadIdx.x];
    __syncthreads();

    int grp = threadIdx.x >> 3;       // 64 nodes per block
    int lane = threadIdx.x & 7;
    int node = blockIdx.x * 64 + grp;
    if (node >= N) node = N - 1;

    int beg = row[node], end = row[node + 1];
    const float4* x4 = reinterpret_cast<const float4*>(x2t);

    float4 a0 = make_float4(0.f, 0.f, 0.f, 0.f);
    float4 a1 = a0, a2 = a0, a3 = a0;
    int e = beg;
    for (; e + 3 < end; e += 4) {
        int s0 = csr[e], s1 = csr[e + 1], s2 = csr[e + 2], s3 = csr[e + 3];
        float4 v0 = x4[(size_t)s0 * 8 + lane];
        float4 v1 = x4[(size_t)s1 * 8 + lane];
        float4 v2 = x4[(size_t)s2 * 8 + lane];
        float4 v3 = x4[(size_t)s3 * 8 + lane];
        a0.x += v0.x; a0.y += v0.y; a0.z += v0.z; a0.w += v0.w;
        a1.x += v1.x; a1.y += v1.y; a1.z += v1.z; a1.w += v1.w;
        a2.x += v2.x; a2.y += v2.y; a2.z += v2.z; a2.w += v2.w;
        a3.x += v3.x; a3.y += v3.y; a3.z += v3.z; a3.w += v3.w;
    }
    for (; e < end; e++) {
        int s0 = csr[e];
        float4 v0 = x4[(size_t)s0 * 8 + lane];
        a0.x += v0.x; a0.y += v0.y; a0.z += v0.z; a0.w += v0.w;
    }
    float inv = 1.0f / fmaxf((float)(end - beg), 1.0f);
    int j = lane * 4;
    float h0 = fmaxf(fmaf(a0.x + a1.x + a2.x + a3.x, inv, bs[j + 0]), 0.f);
    float h1 = fmaxf(fmaf(a0.y + a1.y + a2.y + a3.y, inv, bs[j + 1]), 0.f);
    float h2 = fmaxf(fmaf(a0.z + a1.z + a2.z + a3.z, inv, bs[j + 2]), 0.f);
    float h3 = fmaxf(fmaf(a0.w + a1.w + a2.w + a3.w, inv, bs[j + 3]), 0.f);

    float v = (h0 + h1) + (h2 + h3);
#pragma unroll
    for (int off = 4; off > 0; off >>= 1)
        v += __shfl_down_sync(0xffffffffu, v, off, 8);

    if (lane == 0) {
        float m = v * (1.0f / (float)D2);
        float z = fmaf(m, Wd[0], bd[0]);
        out[node] = 1.0f / (1.0f + expf(-z));
    }
}

// ---------------------------------------------------------------------------
extern "C" void kernel_launch(void* const* d_in, const int* in_sizes, int n_in,
                              void* d_out, int out_size) {
    const float* x   = (const float*)d_in[0];
    const int*   src = (const int*)  d_in[1];
    const int*   dst = (const int*)  d_in[2];
    const float* W1  = (const float*)d_in[3];
    const float* b1  = (const float*)d_in[4];
    const float* W2  = (const float*)d_in[5];
    const float* b2  = (const float*)d_in[6];
    const float* Wd  = (const float*)d_in[7];
    const float* bd  = (const float*)d_in[8];
    float* out = (float*)d_out;

    const int N = in_sizes[0] / D1;
    const int E = in_sizes[1];

    float *x2t;
    int *cnt, *row, *cur, *csr;
    cudaGetSymbolAddress((void**)&x2t, g_x2t);
    cudaGetSymbolAddress((void**)&cnt, g_cnt);
    cudaGetSymbolAddress((void**)&row, g_row);
    cudaGetSymbolAddress((void**)&cur, g_cur);
    cudaGetSymbolAddress((void**)&csr, g_csr);

    // --- CSR build (4 nodes) ---
    cudaMemsetAsync(cnt, 0, (size_t)N * sizeof(int));
    hist_kernel<<<(E + 255) / 256, 256>>>(dst, cnt, E);
    scan_all_kernel<<<1, 1024>>>(cnt, row, cur, N, E);
    fill_kernel<<<(E + 255) / 256, 256>>>(src, dst, cur, csr, E);

    // --- fused layers ---
    layer1_kernel<<<(N + 31) / 32, 512>>>(x, csr, row, W1, b1, W2, x2t, N);
    layer2_kernel<<<(N + 63) / 64, 512>>>(x2t, csr, row, b2, Wd, bd, out, N);
}

// round 4
// speedup vs baseline: 2.1576x; 2.1576x over previous
#include <cuda_runtime.h>
#include <math.h>

#define N_NODES_MAX 100000
#define E_MAX       1600000
#define D1 64
#define D2 32
#define SCAN_B 256
#define MAX_BLOCKS_SCAN 1024   // ceil(100000/256)=391 <= 1024

// Scratch (no allocations allowed)
__device__ float g_x2t[(size_t)N_NODES_MAX * D2];  // relu(agg@W1+b1) @ W2, [N,32]
__device__ int   g_cnt [N_NODES_MAX];
__device__ int   g_row [N_NODES_MAX + 1];
__device__ int   g_cur [N_NODES_MAX];
__device__ int   g_csr [E_MAX];
__device__ int   g_bsum[MAX_BLOCKS_SCAN];
__device__ int   g_boff[MAX_BLOCKS_SCAN];

// ---------------------------------------------------------------------------
__global__ void hist_kernel(const int* __restrict__ dst, int* __restrict__ cnt, int E) {
    int i = blockIdx.x * blockDim.x + threadIdx.x;
    if (i < E) atomicAdd(&cnt[dst[i]], 1);
}

// Exclusive scan, stage 1: per-block Hillis-Steele (coalesced).
__global__ void scan1_kernel(const int* __restrict__ cnt, int* __restrict__ row,
                             int* __restrict__ bsum, int N) {
    __shared__ int s[SCAN_B];
    int i = blockIdx.x * SCAN_B + threadIdx.x;
    int v = (i < N) ? cnt[i] : 0;
    s[threadIdx.x] = v;
    __syncthreads();
#pragma unroll
    for (int off = 1; off < SCAN_B; off <<= 1) {
        int t = 0;
        if (threadIdx.x >= off) t = s[threadIdx.x - off];
        __syncthreads();
        if (threadIdx.x >= off) s[threadIdx.x] += t;
        __syncthreads();
    }
    int incl = s[threadIdx.x];
    if (i < N) row[i] = incl - v;
    if (threadIdx.x == SCAN_B - 1) bsum[blockIdx.x] = incl;
}

// Stage 2: single block scans the block sums (exclusive).
__global__ void scan2_kernel(const int* __restrict__ bsum, int* __restrict__ boff, int nb) {
    __shared__ int s[MAX_BLOCKS_SCAN];
    int t = threadIdx.x;
    int v = (t < nb) ? bsum[t] : 0;
    s[t] = v;
    __syncthreads();
#pragma unroll
    for (int off = 1; off < MAX_BLOCKS_SCAN; off <<= 1) {
        int u = 0;
        if (t >= off) u = s[t - off];
        __syncthreads();
        if (t >= off) s[t] += u;
        __syncthreads();
    }
    if (t < nb) boff[t] = s[t] - v;
}

// Stage 3: add block offsets; init cursors; row[N]=E.
__global__ void scan3_kernel(int* __restrict__ row, int* __restrict__ cur,
                             const int* __restrict__ boff, int N, int E) {
    int i = blockIdx.x * blockDim.x + threadIdx.x;
    if (i < N) {
        int r = row[i] + boff[i / SCAN_B];
        row[i] = r;
        cur[i] = r;
    }
    if (i == 0) row[N] = E;
}

__global__ void fill_kernel(const int* __restrict__ src, const int* __restrict__ dst,
                            int* __restrict__ cur, int* __restrict__ csr, int E) {
    int i = blockIdx.x * blockDim.x + threadIdx.x;
    if (i < E) {
        int d = dst[i];
        int p = atomicAdd(&cur[d], 1);
        csr[p] = src[i];
    }
}

// ---------------------------------------------------------------------------
// Fused layer 1 + W2 pre-transform.
// Block = 256 threads, 32 nodes.
//   Phase A: gather mean, 8 lanes per node (each lane owns 8 features).
//   Phase B: x1 = relu(agg@W1+b1), thread tile = 2 nodes x 4 outputs.
//   Phase C: x2t = x1@W2, thread tile = 2 nodes x 2 outputs.
#define L1_PAD 68   // in_s row stride in floats (padding kills bank conflicts)
__global__ void __launch_bounds__(256, 6)
layer1_kernel(const float* __restrict__ x,
              const int*   __restrict__ csr,
              const int*   __restrict__ row,
              const float* __restrict__ W1,   // [64,64] (k, j)
              const float* __restrict__ b1,   // [64]
              const float* __restrict__ W2,   // [64,32] (k, j)
              float*       __restrict__ x2t,  // [N,32]
              int N) {
    __shared__ float W1s[D1 * D1];
    __shared__ float W2s[D1 * D2];
    __shared__ float b1s[D1];
    __shared__ float in_s[32][L1_PAD];

    for (int i = threadIdx.x; i < D1 * D1; i += blockDim.x) W1s[i] = W1[i];
    for (int i = threadIdx.x; i < D1 * D2; i += blockDim.x) W2s[i] = W2[i];
    if (threadIdx.x < D1) b1s[threadIdx.x] = b1[threadIdx.x];
    __syncthreads();

    // ---- Phase A: gather ----
    {
        int nl = threadIdx.x >> 3;       // local node 0..31
        int lane = threadIdx.x & 7;      // feature chunk
        int node = blockIdx.x * 32 + nl;
        if (node >= N) node = N - 1;

        int beg = row[node], end = row[node + 1];
        const float4* x4 = reinterpret_cast<const float4*>(x);

        float4 a0 = make_float4(0.f, 0.f, 0.f, 0.f);
        float4 a1 = a0, a2 = a0, a3 = a0;
        int e = beg;
        for (; e + 1 < end; e += 2) {
            int s0 = csr[e], s1 = csr[e + 1];
            float4 v0 = x4[(size_t)s0 * 16 + lane * 2];
            float4 v1 = x4[(size_t)s0 * 16 + lane * 2 + 1];
            float4 v2 = x4[(size_t)s1 * 16 + lane * 2];
            float4 v3 = x4[(size_t)s1 * 16 + lane * 2 + 1];
            a0.x += v0.x; a0.y += v0.y; a0.z += v0.z; a0.w += v0.w;
            a1.x += v1.x; a1.y += v1.y; a1.z += v1.z; a1.w += v1.w;
            a2.x += v2.x; a2.y += v2.y; a2.z += v2.z; a2.w += v2.w;
            a3.x += v3.x; a3.y += v3.y; a3.z += v3.z; a3.w += v3.w;
        }
        if (e < end) {
            int s0 = csr[e];
            float4 v0 = x4[(size_t)s0 * 16 + lane * 2];
            float4 v1 = x4[(size_t)s0 * 16 + lane * 2 + 1];
            a0.x += v0.x; a0.y += v0.y; a0.z += v0.z; a0.w += v0.w;
            a1.x += v1.x; a1.y += v1.y; a1.z += v1.z; a1.w += v1.w;
        }
        float inv = 1.0f / fmaxf((float)(end - beg), 1.0f);
        float4 r0, r1;
        r0.x = (a0.x + a2.x) * inv; r0.y = (a0.y + a2.y) * inv;
        r0.z = (a0.z + a2.z) * inv; r0.w = (a0.w + a2.w) * inv;
        r1.x = (a1.x + a3.x) * inv; r1.y = (a1.y + a3.y) * inv;
        r1.z = (a1.z + a3.z) * inv; r1.w = (a1.w + a3.w) * inv;
        float4* rp = reinterpret_cast<float4*>(&in_s[nl][0]);
        rp[lane * 2]     = r0;
        rp[lane * 2 + 1] = r1;
    }
    __syncthreads();

    // ---- Phase B: x1 = relu(agg @ W1 + b1), 2 nodes x 4 outputs ----
    int j4 = threadIdx.x & 15;       // output group: j = j4*4
    int np = threadIdx.x >> 4;       // node pair 0..15
    int n0 = np * 2, n1 = n0 + 1;
    int j = j4 * 4;

    float o00 = b1s[j], o01 = b1s[j + 1], o02 = b1s[j + 2], o03 = b1s[j + 3];
    float o10 = o00, o11 = o01, o12 = o02, o13 = o03;
#pragma unroll
    for (int k = 0; k < D1; k++) {
        float4 w = *reinterpret_cast<const float4*>(&W1s[k * D1 + j]);
        float xa = in_s[n0][k];
        float xb = in_s[n1][k];
        o00 = fmaf(xa, w.x, o00); o01 = fmaf(xa, w.y, o01);
        o02 = fmaf(xa, w.z, o02); o03 = fmaf(xa, w.w, o03);
        o10 = fmaf(xb, w.x, o10); o11 = fmaf(xb, w.y, o11);
        o12 = fmaf(xb, w.z, o12); o13 = fmaf(xb, w.w, o13);
    }
    o00 = fmaxf(o00, 0.f); o01 = fmaxf(o01, 0.f);
    o02 = fmaxf(o02, 0.f); o03 = fmaxf(o03, 0.f);
    o10 = fmaxf(o10, 0.f); o11 = fmaxf(o11, 0.f);
    o12 = fmaxf(o12, 0.f); o13 = fmaxf(o13, 0.f);

    __syncthreads();   // everyone done reading agg
    in_s[n0][j + 0] = o00; in_s[n0][j + 1] = o01;
    in_s[n0][j + 2] = o02; in_s[n0][j + 3] = o03;
    in_s[n1][j + 0] = o10; in_s[n1][j + 1] = o11;
    in_s[n1][j + 2] = o12; in_s[n1][j + 3] = o13;
    __syncthreads();   // x1 staged

    // ---- Phase C: x2t = x1 @ W2, 2 nodes x 2 outputs ----
    int j2 = (threadIdx.x & 15) * 2;
    float p00 = 0.f, p01 = 0.f, p10 = 0.f, p11 = 0.f;
#pragma unroll
    for (int k = 0; k < D1; k++) {
        float2 w = *reinterpret_cast<const float2*>(&W2s[k * D2 + j2]);
        float xa = in_s[n0][k];
        float xb = in_s[n1][k];
        p00 = fmaf(xa, w.x, p00); p01 = fmaf(xa, w.y, p01);
        p10 = fmaf(xb, w.x, p10); p11 = fmaf(xb, w.y, p11);
    }
    int node0 = blockIdx.x * 32 + n0;
    int node1 = blockIdx.x * 32 + n1;
    if (node0 >= N) node0 = N - 1;
    if (node1 >= N) node1 = N - 1;
    reinterpret_cast<float2*>(x2t + (size_t)node0 * D2)[j2 >> 1] = make_float2(p00, p01);
    reinterpret_cast<float2*>(x2t + (size_t)node1 * D2)[j2 >> 1] = make_float2(p10, p11);
}

// ---------------------------------------------------------------------------
// Layer 2 + readout: agg2 = mean(x2t[neighbors]); h = relu(agg2 + b2);
// out = sigmoid(mean(h)*Wd + bd). 8 lanes per node.
__global__ void __launch_bounds__(512)
layer2_kernel(const float* __restrict__ x2t,  // [N,32]
              const int*   __restrict__ csr,
              const int*   __restrict__ row,
              const float* __restrict__ b2,
              const float* __restrict__ Wd,
              const float* __restrict__ bd,
              float*       __restrict__ out,  // [N]
              int N) {
    __shared__ float bs[D2];
    if (threadIdx.x < D2) bs[threadIdx.x] = b2[threadIdx.x];
    __syncthreads();

    int grp = threadIdx.x >> 3;       // 64 nodes per block
    int lane = threadIdx.x & 7;
    int node = blockIdx.x * 64 + grp;
    if (node >= N) node = N - 1;

    int beg = row[node], end = row[node + 1];
    const float4* x4 = reinterpret_cast<const float4*>(x2t);

    float4 a0 = make_float4(0.f, 0.f, 0.f, 0.f);
    float4 a1 = a0, a2 = a0, a3 = a0;
    int e = beg;
    for (; e + 3 < end; e += 4) {
        int s0 = csr[e], s1 = csr[e + 1], s2 = csr[e + 2], s3 = csr[e + 3];
        float4 v0 = x4[(size_t)s0 * 8 + lane];
        float4 v1 = x4[(size_t)s1 * 8 + lane];
        float4 v2 = x4[(size_t)s2 * 8 + lane];
        float4 v3 = x4[(size_t)s3 * 8 + lane];
        a0.x += v0.x; a0.y += v0.y; a0.z += v0.z; a0.w += v0.w;
        a1.x += v1.x; a1.y += v1.y; a1.z += v1.z; a1.w += v1.w;
        a2.x += v2.x; a2.y += v2.y; a2.z += v2.z; a2.w += v2.w;
        a3.x += v3.x; a3.y += v3.y; a3.z += v3.z; a3.w += v3.w;
    }
    for (; e < end; e++) {
        int s0 = csr[e];
        float4 v0 = x4[(size_t)s0 * 8 + lane];
        a0.x += v0.x; a0.y += v0.y; a0.z += v0.z; a0.w += v0.w;
    }
    float inv = 1.0f / fmaxf((float)(end - beg), 1.0f);
    int j = lane * 4;
    float h0 = fmaxf(fmaf(a0.x + a1.x + a2.x + a3.x, inv, bs[j + 0]), 0.f);
    float h1 = fmaxf(fmaf(a0.y + a1.y + a2.y + a3.y, inv, bs[j + 1]), 0.f);
    float h2 = fmaxf(fmaf(a0.z + a1.z + a2.z + a3.z, inv, bs[j + 2]), 0.f);
    float h3 = fmaxf(fmaf(a0.w + a1.w + a2.w + a3.w, inv, bs[j + 3]), 0.f);

    float v = (h0 + h1) + (h2 + h3);
#pragma unroll
    for (int off = 4; off > 0; off >>= 1)
        v += __shfl_down_sync(0xffffffffu, v, off, 8);

    if (lane == 0) {
        float m = v * (1.0f / (float)D2);
        float z = fmaf(m, Wd[0], bd[0]);
        out[node] = 1.0f / (1.0f + expf(-z));
    }
}

// ---------------------------------------------------------------------------
extern "C" void kernel_launch(void* const* d_in, const int* in_sizes, int n_in,
                              void* d_out, int out_size) {
    const float* x   = (const float*)d_in[0];
    const int*   src = (const int*)  d_in[1];
    const int*   dst = (const int*)  d_in[2];
    const float* W1  = (const float*)d_in[3];
    const float* b1  = (const float*)d_in[4];
    const float* W2  = (const float*)d_in[5];
    const float* b2  = (const float*)d_in[6];
    const float* Wd  = (const float*)d_in[7];
    const float* bd  = (const float*)d_in[8];
    float* out = (float*)d_out;

    const int N = in_sizes[0] / D1;
    const int E = in_sizes[1];

    float *x2t;
    int *cnt, *row, *cur, *csr, *bsum, *boff;
    cudaGetSymbolAddress((void**)&x2t,  g_x2t);
    cudaGetSymbolAddress((void**)&cnt,  g_cnt);
    cudaGetSymbolAddress((void**)&row,  g_row);
    cudaGetSymbolAddress((void**)&cur,  g_cur);
    cudaGetSymbolAddress((void**)&csr,  g_csr);
    cudaGetSymbolAddress((void**)&bsum, g_bsum);
    cudaGetSymbolAddress((void**)&boff, g_boff);

    const int nb = (N + SCAN_B - 1) / SCAN_B;

    // --- CSR build (coalesced multi-block scan) ---
    cudaMemsetAsync(cnt, 0, (size_t)N * sizeof(int));
    hist_kernel<<<(E + 255) / 256, 256>>>(dst, cnt, E);
    scan1_kernel<<<nb, SCAN_B>>>(cnt, row, bsum, N);
    scan2_kernel<<<1, MAX_BLOCKS_SCAN>>>(bsum, boff, nb);
    scan3_kernel<<<(N + 255) / 256, 256>>>(row, cur, boff, N, E);
    fill_kernel<<<(E + 255) / 256, 256>>>(src, dst, cur, csr, E);

    // --- fused layers ---
    layer1_kernel<<<(N + 31) / 32, 256>>>(x, csr, row, W1, b1, W2, x2t, N);
    layer2_kernel<<<(N + 63) / 64, 512>>>(x2t, csr, row, b2, Wd, bd, out, N);
}

// round 6
// speedup vs baseline: 2.4963x; 1.1570x over previous
#include <cuda_runtime.h>
#include <cuda_fp16.h>
#include <cstdint>
#include <math.h>

#define N_NODES_MAX 100000
#define E_MAX       1600000
#define D1 64
#define D2 32
#define SCAN_B 256

// Scratch (no allocations allowed)
__device__ __half g_xh  [(size_t)N_NODES_MAX * D1];  // fp16 copy of input features
__device__ __half g_x2th[(size_t)N_NODES_MAX * D2];  // fp16 (relu(agg@W1+b1))@W2
__device__ int    g_cnt [N_NODES_MAX];
__device__ int    g_row [N_NODES_MAX + 1];
__device__ int    g_cur [N_NODES_MAX];
__device__ int    g_csr [E_MAX];
__device__ int    g_bsum[1024];

// ---------------------------------------------------------------------------
// Convert x (fp32) -> xh (fp16), vectorized 4 floats -> 4 halves per thread.
__global__ void conv_kernel(const float4* __restrict__ x4,
                            uint2* __restrict__ xh, int n4) {
    int i = blockIdx.x * blockDim.x + threadIdx.x;
    if (i < n4) {
        float4 v = x4[i];
        __half2 a = __floats2half2_rn(v.x, v.y);
        __half2 b = __floats2half2_rn(v.z, v.w);
        uint2 o;
        o.x = *reinterpret_cast<unsigned int*>(&a);
        o.y = *reinterpret_cast<unsigned int*>(&b);
        xh[i] = o;
    }
}

// ---------------------------------------------------------------------------
__global__ void hist_kernel(const int* __restrict__ dst, int* __restrict__ cnt, int E) {
    int i = blockIdx.x * blockDim.x + threadIdx.x;
    if (i < E) atomicAdd(&cnt[dst[i]], 1);
}

// Scan stage 1: per-block Hillis-Steele (coalesced), block totals to bsum.
__global__ void scan1_kernel(const int* __restrict__ cnt, int* __restrict__ row,
                             int* __restrict__ bsum, int N) {
    __shared__ int s[SCAN_B];
    int i = blockIdx.x * SCAN_B + threadIdx.x;
    int v = (i < N) ? cnt[i] : 0;
    s[threadIdx.x] = v;
    __syncthreads();
#pragma unroll
    for (int off = 1; off < SCAN_B; off <<= 1) {
        int t = 0;
        if (threadIdx.x >= off) t = s[threadIdx.x - off];
        __syncthreads();
        if (threadIdx.x >= off) s[threadIdx.x] += t;
        __syncthreads();
    }
    int incl = s[threadIdx.x];
    if (i < N) row[i] = incl - v;
    if (threadIdx.x == SCAN_B - 1) bsum[blockIdx.x] = incl;
}

// Scan stages 2+3 merged: each block sums its bsum prefix itself (<=391 ints,
// L2-resident) then finalizes row and cursors.
__global__ void scan23_kernel(int* __restrict__ row, int* __restrict__ cur,
                              const int* __restrict__ bsum, int N, int E) {
    __shared__ int part[SCAN_B];
    int acc = 0;
    for (int i = threadIdx.x; i < blockIdx.x; i += SCAN_B) acc += bsum[i];
    part[threadIdx.x] = acc;
    __syncthreads();
#pragma unroll
    for (int off = SCAN_B / 2; off > 0; off >>= 1) {
        if (threadIdx.x < off) part[threadIdx.x] += part[threadIdx.x + off];
        __syncthreads();
    }
    int boff = part[0];
    int i = blockIdx.x * SCAN_B + threadIdx.x;
    if (i < N) {
        int r = row[i] + boff;
        row[i] = r;
        cur[i] = r;
    }
    if (blockIdx.x == 0 && threadIdx.x == 0) row[N] = E;
}

__global__ void fill_kernel(const int* __restrict__ src, const int* __restrict__ dst,
                            int* __restrict__ cur, int* __restrict__ csr, int E) {
    int i = blockIdx.x * blockDim.x + threadIdx.x;
    if (i < E) {
        int d = dst[i];
        int p = atomicAdd(&cur[d], 1);
        csr[p] = src[i];
    }
}

// ---------------------------------------------------------------------------
__device__ __forceinline__ void acc_h8(float* acc, uint4 v) {
    float2 f;
    f = __half22float2(*reinterpret_cast<__half2*>(&v.x)); acc[0] += f.x; acc[1] += f.y;
    f = __half22float2(*reinterpret_cast<__half2*>(&v.y)); acc[2] += f.x; acc[3] += f.y;
    f = __half22float2(*reinterpret_cast<__half2*>(&v.z)); acc[4] += f.x; acc[5] += f.y;
    f = __half22float2(*reinterpret_cast<__half2*>(&v.w)); acc[6] += f.x; acc[7] += f.y;
}

// Fused layer 1 + W2 pre-transform. Block = 256 threads, 32 nodes.
//   Phase A: fp16 gather mean, 8 lanes/node, each lane owns 8 features (16B).
//   Phase B: x1 = relu(agg@W1+b1), tile = 2 nodes x 4 outputs.
//   Phase C: x2t = x1@W2 (fp16 store), tile = 2 nodes x 2 outputs.
#define L1_PAD 68
__global__ void __launch_bounds__(256, 6)
layer1_kernel(const __half* __restrict__ xh,
              const int*    __restrict__ csr,
              const int*    __restrict__ row,
              const float*  __restrict__ W1,   // [64,64] (k, j)
              const float*  __restrict__ b1,   // [64]
              const float*  __restrict__ W2,   // [64,32] (k, j)
              __half*       __restrict__ x2th, // [N,32] fp16
              int N) {
    __shared__ float W1s[D1 * D1];
    __shared__ float W2s[D1 * D2];
    __shared__ float b1s[D1];
    __shared__ float in_s[32][L1_PAD];

    for (int i = threadIdx.x; i < D1 * D1; i += blockDim.x) W1s[i] = W1[i];
    for (int i = threadIdx.x; i < D1 * D2; i += blockDim.x) W2s[i] = W2[i];
    if (threadIdx.x < D1) b1s[threadIdx.x] = b1[threadIdx.x];
    __syncthreads();

    // ---- Phase A: fp16 gather ----
    {
        int nl = threadIdx.x >> 3;
        int lane = threadIdx.x & 7;
        int node = blockIdx.x * 32 + nl;
        if (node >= N) node = N - 1;

        int beg = row[node], end = row[node + 1];
        const uint4* xh4 = reinterpret_cast<const uint4*>(xh);  // row stride 8

        float acc[8];
#pragma unroll
        for (int i = 0; i < 8; i++) acc[i] = 0.f;

        int e = beg;
        for (; e + 3 < end; e += 4) {
            int s0 = csr[e], s1 = csr[e + 1], s2 = csr[e + 2], s3 = csr[e + 3];
            uint4 v0 = xh4[(size_t)s0 * 8 + lane];
            uint4 v1 = xh4[(size_t)s1 * 8 + lane];
            uint4 v2 = xh4[(size_t)s2 * 8 + lane];
            uint4 v3 = xh4[(size_t)s3 * 8 + lane];
            acc_h8(acc, v0); acc_h8(acc, v1); acc_h8(acc, v2); acc_h8(acc, v3);
        }
        for (; e < end; e++) {
            uint4 v0 = xh4[(size_t)csr[e] * 8 + lane];
            acc_h8(acc, v0);
        }
        float inv = 1.0f / fmaxf((float)(end - beg), 1.0f);
        float4 r0 = make_float4(acc[0] * inv, acc[1] * inv, acc[2] * inv, acc[3] * inv);
        float4 r1 = make_float4(acc[4] * inv, acc[5] * inv, acc[6] * inv, acc[7] * inv);
        float4* rp = reinterpret_cast<float4*>(&in_s[nl][0]);
        rp[lane * 2]     = r0;
        rp[lane * 2 + 1] = r1;
    }
    __syncthreads();

    // ---- Phase B: x1 = relu(agg @ W1 + b1), 2 nodes x 4 outputs ----
    int j4 = threadIdx.x & 15;
    int np = threadIdx.x >> 4;
    int n0 = np * 2, n1 = n0 + 1;
    int j = j4 * 4;

    float o00 = b1s[j], o01 = b1s[j + 1], o02 = b1s[j + 2], o03 = b1s[j + 3];
    float o10 = o00, o11 = o01, o12 = o02, o13 = o03;
#pragma unroll
    for (int k = 0; k < D1; k++) {
        float4 w = *reinterpret_cast<const float4*>(&W1s[k * D1 + j]);
        float xa = in_s[n0][k];
        float xb = in_s[n1][k];
        o00 = fmaf(xa, w.x, o00); o01 = fmaf(xa, w.y, o01);
        o02 = fmaf(xa, w.z, o02); o03 = fmaf(xa, w.w, o03);
        o10 = fmaf(xb, w.x, o10); o11 = fmaf(xb, w.y, o11);
        o12 = fmaf(xb, w.z, o12); o13 = fmaf(xb, w.w, o13);
    }
    o00 = fmaxf(o00, 0.f); o01 = fmaxf(o01, 0.f);
    o02 = fmaxf(o02, 0.f); o03 = fmaxf(o03, 0.f);
    o10 = fmaxf(o10, 0.f); o11 = fmaxf(o11, 0.f);
    o12 = fmaxf(o12, 0.f); o13 = fmaxf(o13, 0.f);

    __syncthreads();
    in_s[n0][j + 0] = o00; in_s[n0][j + 1] = o01;
    in_s[n0][j + 2] = o02; in_s[n0][j + 3] = o03;
    in_s[n1][j + 0] = o10; in_s[n1][j + 1] = o11;
    in_s[n1][j + 2] = o12; in_s[n1][j + 3] = o13;
    __syncthreads();

    // ---- Phase C: x2t = x1 @ W2 (fp16 store), 2 nodes x 2 outputs ----
    int j2 = (threadIdx.x & 15) * 2;
    float p00 = 0.f, p01 = 0.f, p10 = 0.f, p11 = 0.f;
#pragma unroll
    for (int k = 0; k < D1; k++) {
        float2 w = *reinterpret_cast<const float2*>(&W2s[k * D2 + j2]);
        float xa = in_s[n0][k];
        float xb = in_s[n1][k];
        p00 = fmaf(xa, w.x, p00); p01 = fmaf(xa, w.y, p01);
        p10 = fmaf(xb, w.x, p10); p11 = fmaf(xb, w.y, p11);
    }
    int node0 = blockIdx.x * 32 + n0;
    int node1 = blockIdx.x * 32 + n1;
    if (node0 >= N) node0 = N - 1;
    if (node1 >= N) node1 = N - 1;
    *reinterpret_cast<__half2*>(x2th + (size_t)node0 * D2 + j2) = __floats2half2_rn(p00, p01);
    *reinterpret_cast<__half2*>(x2th + (size_t)node1 * D2 + j2) = __floats2half2_rn(p10, p11);
}

// ---------------------------------------------------------------------------
// Layer 2 + readout (fp16 gather): agg2 = mean(x2t[nb]); h = relu(agg2+b2);
// out = sigmoid(mean(h)*Wd + bd). 8 lanes per node, each lane 4 features (8B).
__global__ void __launch_bounds__(512)
layer2_kernel(const __half* __restrict__ x2th,  // [N,32] fp16
              const int*    __restrict__ csr,
              const int*    __restrict__ row,
              const float*  __restrict__ b2,
              const float*  __restrict__ Wd,
              const float*  __restrict__ bd,
              float*        __restrict__ out,   // [N]
              int N) {
    __shared__ float bs[D2];
    if (threadIdx.x < D2) bs[threadIdx.x] = b2[threadIdx.x];
    __syncthreads();

    int grp = threadIdx.x >> 3;
    int lane = threadIdx.x & 7;
    int node = blockIdx.x * 64 + grp;
    if (node >= N) node = N - 1;

    int beg = row[node], end = row[node + 1];
    const uint2* x2 = reinterpret_cast<const uint2*>(x2th);  // row stride 8

    float a0 = 0.f, a1 = 0.f, a2 = 0.f, a3 = 0.f;
    int e = beg;
    for (; e + 3 < end; e += 4) {
        int s0 = csr[e], s1 = csr[e + 1], s2 = csr[e + 2], s3 = csr[e + 3];
        uint2 v0 = x2[(size_t)s0 * 8 + lane];
        uint2 v1 = x2[(size_t)s1 * 8 + lane];
        uint2 v2 = x2[(size_t)s2 * 8 + lane];
        uint2 v3 = x2[(size_t)s3 * 8 + lane];
        float2 f;
        f = __half22float2(*reinterpret_cast<__half2*>(&v0.x)); a0 += f.x; a1 += f.y;
        f = __half22float2(*reinterpret_cast<__half2*>(&v0.y)); a2 += f.x; a3 += f.y;
        f = __half22float2(*reinterpret_cast<__half2*>(&v1.x)); a0 += f.x; a1 += f.y;
        f = __half22float2(*reinterpret_cast<__half2*>(&v1.y)); a2 += f.x; a3 += f.y;
        f = __half22float2(*reinterpret_cast<__half2*>(&v2.x)); a0 += f.x; a1 += f.y;
        f = __half22float2(*reinterpret_cast<__half2*>(&v2.y)); a2 += f.x; a3 += f.y;
        f = __half22float2(*reinterpret_cast<__half2*>(&v3.x)); a0 += f.x; a1 += f.y;
        f = __half22float2(*reinterpret_cast<__half2*>(&v3.y)); a2 += f.x; a3 += f.y;
    }
    for (; e < end; e++) {
        uint2 v0 = x2[(size_t)csr[e] * 8 + lane];
        float2 f;
        f = __half22float2(*reinterpret_cast<__half2*>(&v0.x)); a0 += f.x; a1 += f.y;
        f = __half22float2(*reinterpret_cast<__half2*>(&v0.y)); a2 += f.x; a3 += f.y;
    }
    float inv = 1.0f / fmaxf((float)(end - beg), 1.0f);
    int j = lane * 4;
    float h0 = fmaxf(fmaf(a0, inv, bs[j + 0]), 0.f);
    float h1 = fmaxf(fmaf(a1, inv, bs[j + 1]), 0.f);
    float h2 = fmaxf(fmaf(a2, inv, bs[j + 2]), 0.f);
    float h3 = fmaxf(fmaf(a3, inv, bs[j + 3]), 0.f);

    float v = (h0 + h1) + (h2 + h3);
#pragma unroll
    for (int off = 4; off > 0; off >>= 1)
        v += __shfl_down_sync(0xffffffffu, v, off, 8);

    if (lane == 0) {
        float m = v * (1.0f / (float)D2);
        float z = fmaf(m, Wd[0], bd[0]);
        out[node] = 1.0f / (1.0f + expf(-z));
    }
}

// ---------------------------------------------------------------------------
extern "C" void kernel_launch(void* const* d_in, const int* in_sizes, int n_in,
                              void* d_out, int out_size) {
    const float* x   = (const float*)d_in[0];
    const int*   src = (const int*)  d_in[1];
    const int*   dst = (const int*)  d_in[2];
    const float* W1  = (const float*)d_in[3];
    const float* b1  = (const float*)d_in[4];
    const float* W2  = (const float*)d_in[5];
    const float* b2  = (const float*)d_in[6];
    const float* Wd  = (const float*)d_in[7];
    const float* bd  = (const float*)d_in[8];
    float* out = (float*)d_out;

    const int N = in_sizes[0] / D1;
    const int E = in_sizes[1];

    __half *xh, *x2th;
    int *cnt, *row, *cur, *csr, *bsum;
    cudaGetSymbolAddress((void**)&xh,   g_xh);
    cudaGetSymbolAddress((void**)&x2th, g_x2th);
    cudaGetSymbolAddress((void**)&cnt,  g_cnt);
    cudaGetSymbolAddress((void**)&row,  g_row);
    cudaGetSymbolAddress((void**)&cur,  g_cur);
    cudaGetSymbolAddress((void**)&csr,  g_csr);
    cudaGetSymbolAddress((void**)&bsum, g_bsum);

    const int nb = (N + SCAN_B - 1) / SCAN_B;
    const int n4 = N * (D1 / 4);

    // --- CSR build + fp16 conversion ---
    cudaMemsetAsync(cnt, 0, (size_t)N * sizeof(int));
    conv_kernel<<<(n4 + 255) / 256, 256>>>(
        reinterpret_cast<const float4*>(x), reinterpret_cast<uint2*>(xh), n4);
    hist_kernel<<<(E + 255) / 256, 256>>>(dst, cnt, E);
    scan1_kernel<<<nb, SCAN_B>>>(cnt, row, bsum, N);
    scan23_kernel<<<nb, SCAN_B>>>(row, cur, bsum, N, E);
    fill_kernel<<<(E + 255) / 256, 256>>>(src, dst, cur, csr, E);

    // --- fused layers ---
    layer1_kernel<<<(N + 31) / 32, 256>>>(xh, csr, row, W1, b1, W2, x2th, N);
    layer2_kernel<<<(N + 63) / 64, 512>>>(x2th, csr, row, b2, Wd, bd, out, N);
}

// round 7
// speedup vs baseline: 2.4981x; 1.0007x over previous
#include <cuda_runtime.h>
#include <cuda_fp16.h>
#include <cstdint>
#include <math.h>

#define N_NODES_MAX 100000
#define E_MAX       1600000
#define D1 64
#define D2 32
#define SCAN_B 512

// Scratch (no allocations allowed)
__device__ __half g_xh  [(size_t)N_NODES_MAX * D1];  // fp16 copy of input features
__device__ __half g_x2th[(size_t)N_NODES_MAX * D2];  // fp16 (relu(agg@W1+b1))@W2
__device__ int    g_cnt [N_NODES_MAX];
__device__ int    g_row [N_NODES_MAX + 1];
__device__ int    g_cur [N_NODES_MAX];
__device__ int    g_csr [E_MAX];
__device__ int    g_bsum[1024];

// ---------------------------------------------------------------------------
// Packed f32x2 helpers (Blackwell FFMA2 — PTX-only, ptxas won't auto-fuse).
__device__ __forceinline__ unsigned long long pack2(float lo, float hi) {
    unsigned long long r;
    asm("mov.b64 %0, {%1, %2};"
        : "=l"(r) : "r"(__float_as_uint(lo)), "r"(__float_as_uint(hi)));
    return r;
}
__device__ __forceinline__ void unpack2(unsigned long long v, float& lo, float& hi) {
    unsigned int a, b;
    asm("mov.b64 {%0, %1}, %2;" : "=r"(a), "=r"(b) : "l"(v));
    lo = __uint_as_float(a);
    hi = __uint_as_float(b);
}
__device__ __forceinline__ unsigned long long fma2(unsigned long long a,
                                                   unsigned long long b,
                                                   unsigned long long c) {
    unsigned long long d;
    asm("fma.rn.f32x2 %0, %1, %2, %3;" : "=l"(d) : "l"(a), "l"(b), "l"(c));
    return d;
}

// ---------------------------------------------------------------------------
// Convert x (fp32) -> xh (fp16); also zeroes the degree histogram (grid is
// 16x larger than N, so the first N threads cover it).
__global__ void conv_kernel(const float4* __restrict__ x4,
                            uint2* __restrict__ xh,
                            int* __restrict__ cnt, int n4, int N) {
    int i = blockIdx.x * blockDim.x + threadIdx.x;
    if (i < n4) {
        float4 v = x4[i];
        __half2 a = __floats2half2_rn(v.x, v.y);
        __half2 b = __floats2half2_rn(v.z, v.w);
        uint2 o;
        o.x = *reinterpret_cast<unsigned int*>(&a);
        o.y = *reinterpret_cast<unsigned int*>(&b);
        xh[i] = o;
    }
    if (i < N) cnt[i] = 0;
}

// ---------------------------------------------------------------------------
__global__ void hist_kernel(const int* __restrict__ dst, int* __restrict__ cnt, int E) {
    int i = blockIdx.x * blockDim.x + threadIdx.x;
    if (i < E) atomicAdd(&cnt[dst[i]], 1);
}

// Scan stage 1: per-block Hillis-Steele (coalesced), block totals to bsum.
__global__ void __launch_bounds__(SCAN_B)
scan1_kernel(const int* __restrict__ cnt, int* __restrict__ row,
             int* __restrict__ bsum, int N) {
    __shared__ int s[SCAN_B];
    int i = blockIdx.x * SCAN_B + threadIdx.x;
    int v = (i < N) ? cnt[i] : 0;
    s[threadIdx.x] = v;
    __syncthreads();
#pragma unroll
    for (int off = 1; off < SCAN_B; off <<= 1) {
        int t = 0;
        if (threadIdx.x >= off) t = s[threadIdx.x - off];
        __syncthreads();
        if (threadIdx.x >= off) s[threadIdx.x] += t;
        __syncthreads();
    }
    int incl = s[threadIdx.x];
    if (i < N) row[i] = incl - v;
    if (threadIdx.x == SCAN_B - 1) bsum[blockIdx.x] = incl;
}

// Scan stages 2+3 merged: each block sums its bsum prefix itself (<=196 ints,
// L2-resident) then finalizes row and cursors.
__global__ void __launch_bounds__(SCAN_B)
scan23_kernel(int* __restrict__ row, int* __restrict__ cur,
              const int* __restrict__ bsum, int N, int E) {
    __shared__ int part[SCAN_B];
    int acc = 0;
    for (int i = threadIdx.x; i < blockIdx.x; i += SCAN_B) acc += bsum[i];
    part[threadIdx.x] = acc;
    __syncthreads();
#pragma unroll
    for (int off = SCAN_B / 2; off > 0; off >>= 1) {
        if (threadIdx.x < off) part[threadIdx.x] += part[threadIdx.x + off];
        __syncthreads();
    }
    int boff = part[0];
    int i = blockIdx.x * SCAN_B + threadIdx.x;
    if (i < N) {
        int r = row[i] + boff;
        row[i] = r;
        cur[i] = r;
    }
    if (blockIdx.x == 0 && threadIdx.x == 0) row[N] = E;
}

__global__ void fill_kernel(const int* __restrict__ src, const int* __restrict__ dst,
                            int* __restrict__ cur, int* __restrict__ csr, int E) {
    int i = blockIdx.x * blockDim.x + threadIdx.x;
    if (i < E) {
        int d = dst[i];
        int p = atomicAdd(&cur[d], 1);
        csr[p] = src[i];
    }
}

// ---------------------------------------------------------------------------
__device__ __forceinline__ void acc_h8(float* acc, uint4 v) {
    float2 f;
    f = __half22float2(*reinterpret_cast<__half2*>(&v.x)); acc[0] += f.x; acc[1] += f.y;
    f = __half22float2(*reinterpret_cast<__half2*>(&v.y)); acc[2] += f.x; acc[3] += f.y;
    f = __half22float2(*reinterpret_cast<__half2*>(&v.z)); acc[4] += f.x; acc[5] += f.y;
    f = __half22float2(*reinterpret_cast<__half2*>(&v.w)); acc[6] += f.x; acc[7] += f.y;
}

// Fused layer 1 + W2 pre-transform. Block = 256 threads, 32 nodes.
//   Phase A: fp16 gather mean, 8 lanes/node, each lane owns 8 features (16B).
//   Phase B: x1 = relu(agg@W1+b1), tile = 2 nodes x 4 outputs, packed f32x2.
//   Phase C: x2t = x1@W2 (fp16 store), tile = 2 nodes x 2 outputs, f32x2.
#define L1_PAD 68
__global__ void __launch_bounds__(256, 6)
layer1_kernel(const __half* __restrict__ xh,
              const int*    __restrict__ csr,
              const int*    __restrict__ row,
              const float*  __restrict__ W1,   // [64,64] (k, j)
              const float*  __restrict__ b1,   // [64]
              const float*  __restrict__ W2,   // [64,32] (k, j)
              __half*       __restrict__ x2th, // [N,32] fp16
              int N) {
    __shared__ float W1s[D1 * D1];
    __shared__ float W2s[D1 * D2];
    __shared__ float b1s[D1];
    __shared__ float in_s[32][L1_PAD];

    for (int i = threadIdx.x; i < D1 * D1; i += blockDim.x) W1s[i] = W1[i];
    for (int i = threadIdx.x; i < D1 * D2; i += blockDim.x) W2s[i] = W2[i];
    if (threadIdx.x < D1) b1s[threadIdx.x] = b1[threadIdx.x];
    __syncthreads();

    // ---- Phase A: fp16 gather ----
    {
        int nl = threadIdx.x >> 3;
        int lane = threadIdx.x & 7;
        int node = blockIdx.x * 32 + nl;
        if (node >= N) node = N - 1;

        int beg = row[node], end = row[node + 1];
        const uint4* xh4 = reinterpret_cast<const uint4*>(xh);  // row stride 8

        float acc[8];
#pragma unroll
        for (int i = 0; i < 8; i++) acc[i] = 0.f;

        int e = beg;
        for (; e + 3 < end; e += 4) {
            int s0 = csr[e], s1 = csr[e + 1], s2 = csr[e + 2], s3 = csr[e + 3];
            uint4 v0 = xh4[(size_t)s0 * 8 + lane];
            uint4 v1 = xh4[(size_t)s1 * 8 + lane];
            uint4 v2 = xh4[(size_t)s2 * 8 + lane];
            uint4 v3 = xh4[(size_t)s3 * 8 + lane];
            acc_h8(acc, v0); acc_h8(acc, v1); acc_h8(acc, v2); acc_h8(acc, v3);
        }
        for (; e < end; e++) {
            uint4 v0 = xh4[(size_t)csr[e] * 8 + lane];
            acc_h8(acc, v0);
        }
        float inv = 1.0f / fmaxf((float)(end - beg), 1.0f);
        float4 r0 = make_float4(acc[0] * inv, acc[1] * inv, acc[2] * inv, acc[3] * inv);
        float4 r1 = make_float4(acc[4] * inv, acc[5] * inv, acc[6] * inv, acc[7] * inv);
        float4* rp = reinterpret_cast<float4*>(&in_s[nl][0]);
        rp[lane * 2]     = r0;
        rp[lane * 2 + 1] = r1;
    }
    __syncthreads();

    // ---- Phase B: x1 = relu(agg @ W1 + b1), 2 nodes packed into f32x2 ----
    int j4 = threadIdx.x & 15;
    int np = threadIdx.x >> 4;
    int n0 = np * 2, n1 = n0 + 1;
    int j = j4 * 4;

    unsigned long long o0 = pack2(b1s[j + 0], b1s[j + 0]);
    unsigned long long o1 = pack2(b1s[j + 1], b1s[j + 1]);
    unsigned long long o2 = pack2(b1s[j + 2], b1s[j + 2]);
    unsigned long long o3 = pack2(b1s[j + 3], b1s[j + 3]);
#pragma unroll
    for (int k = 0; k < D1; k++) {
        float4 w = *reinterpret_cast<const float4*>(&W1s[k * D1 + j]);
        unsigned long long xab = pack2(in_s[n0][k], in_s[n1][k]);
        o0 = fma2(xab, pack2(w.x, w.x), o0);
        o1 = fma2(xab, pack2(w.y, w.y), o1);
        o2 = fma2(xab, pack2(w.z, w.z), o2);
        o3 = fma2(xab, pack2(w.w, w.w), o3);
    }
    float o00, o10, o01, o11, o02, o12, o03, o13;
    unpack2(o0, o00, o10);
    unpack2(o1, o01, o11);
    unpack2(o2, o02, o12);
    unpack2(o3, o03, o13);
    o00 = fmaxf(o00, 0.f); o01 = fmaxf(o01, 0.f);
    o02 = fmaxf(o02, 0.f); o03 = fmaxf(o03, 0.f);
    o10 = fmaxf(o10, 0.f); o11 = fmaxf(o11, 0.f);
    o12 = fmaxf(o12, 0.f); o13 = fmaxf(o13, 0.f);

    __syncthreads();
    in_s[n0][j + 0] = o00; in_s[n0][j + 1] = o01;
    in_s[n0][j + 2] = o02; in_s[n0][j + 3] = o03;
    in_s[n1][j + 0] = o10; in_s[n1][j + 1] = o11;
    in_s[n1][j + 2] = o12; in_s[n1][j + 3] = o13;
    __syncthreads();

    // ---- Phase C: x2t = x1 @ W2 (fp16 store), 2 nodes packed f32x2 ----
    int j2 = (threadIdx.x & 15) * 2;
    unsigned long long p0 = 0ull, p1 = 0ull;   // (0.0f, 0.0f) packed
#pragma unroll
    for (int k = 0; k < D1; k++) {
        float2 w = *reinterpret_cast<const float2*>(&W2s[k * D2 + j2]);
        unsigned long long xab = pack2(in_s[n0][k], in_s[n1][k]);
        p0 = fma2(xab, pack2(w.x, w.x), p0);
        p1 = fma2(xab, pack2(w.y, w.y), p1);
    }
    float p00, p10, p01, p11;
    unpack2(p0, p00, p10);
    unpack2(p1, p01, p11);

    int node0 = blockIdx.x * 32 + n0;
    int node1 = blockIdx.x * 32 + n1;
    if (node0 >= N) node0 = N - 1;
    if (node1 >= N) node1 = N - 1;
    *reinterpret_cast<__half2*>(x2th + (size_t)node0 * D2 + j2) = __floats2half2_rn(p00, p01);
    *reinterpret_cast<__half2*>(x2th + (size_t)node1 * D2 + j2) = __floats2half2_rn(p10, p11);
}

// ---------------------------------------------------------------------------
// Layer 2 + readout (fp16 gather): agg2 = mean(x2t[nb]); h = relu(agg2+b2);
// out = sigmoid(mean(h)*Wd + bd). 8 lanes per node, each lane 4 features (8B).
__global__ void __launch_bounds__(512)
layer2_kernel(const __half* __restrict__ x2th,  // [N,32] fp16
              const int*    __restrict__ csr,
              const int*    __restrict__ row,
              const float*  __restrict__ b2,
              const float*  __restrict__ Wd,
              const float*  __restrict__ bd,
              float*        __restrict__ out,   // [N]
              int N) {
    __shared__ float bs[D2];
    if (threadIdx.x < D2) bs[threadIdx.x] = b2[threadIdx.x];
    __syncthreads();

    int grp = threadIdx.x >> 3;
    int lane = threadIdx.x & 7;
    int node = blockIdx.x * 64 + grp;
    if (node >= N) node = N - 1;

    int beg = row[node], end = row[node + 1];
    const uint2* x2 = reinterpret_cast<const uint2*>(x2th);  // row stride 8

    float a0 = 0.f, a1 = 0.f, a2 = 0.f, a3 = 0.f;
    int e = beg;
    for (; e + 3 < end; e += 4) {
        int s0 = csr[e], s1 = csr[e + 1], s2 = csr[e + 2], s3 = csr[e + 3];
        uint2 v0 = x2[(size_t)s0 * 8 + lane];
        uint2 v1 = x2[(size_t)s1 * 8 + lane];
        uint2 v2 = x2[(size_t)s2 * 8 + lane];
        uint2 v3 = x2[(size_t)s3 * 8 + lane];
        float2 f;
        f = __half22float2(*reinterpret_cast<__half2*>(&v0.x)); a0 += f.x; a1 += f.y;
        f = __half22float2(*reinterpret_cast<__half2*>(&v0.y)); a2 += f.x; a3 += f.y;
        f = __half22float2(*reinterpret_cast<__half2*>(&v1.x)); a0 += f.x; a1 += f.y;
        f = __half22float2(*reinterpret_cast<__half2*>(&v1.y)); a2 += f.x; a3 += f.y;
        f = __half22float2(*reinterpret_cast<__half2*>(&v2.x)); a0 += f.x; a1 += f.y;
        f = __half22float2(*reinterpret_cast<__half2*>(&v2.y)); a2 += f.x; a3 += f.y;
        f = __half22float2(*reinterpret_cast<__half2*>(&v3.x)); a0 += f.x; a1 += f.y;
        f = __half22float2(*reinterpret_cast<__half2*>(&v3.y)); a2 += f.x; a3 += f.y;
    }
    for (; e < end; e++) {
        uint2 v0 = x2[(size_t)csr[e] * 8 + lane];
        float2 f;
        f = __half22float2(*reinterpret_cast<__half2*>(&v0.x)); a0 += f.x; a1 += f.y;
        f = __half22float2(*reinterpret_cast<__half2*>(&v0.y)); a2 += f.x; a3 += f.y;
    }
    float inv = 1.0f / fmaxf((float)(end - beg), 1.0f);
    int j = lane * 4;
    float h0 = fmaxf(fmaf(a0, inv, bs[j + 0]), 0.f);
    float h1 = fmaxf(fmaf(a1, inv, bs[j + 1]), 0.f);
    float h2 = fmaxf(fmaf(a2, inv, bs[j + 2]), 0.f);
    float h3 = fmaxf(fmaf(a3, inv, bs[j + 3]), 0.f);

    float v = (h0 + h1) + (h2 + h3);
#pragma unroll
    for (int off = 4; off > 0; off >>= 1)
        v += __shfl_down_sync(0xffffffffu, v, off, 8);

    if (lane == 0) {
        float m = v * (1.0f / (float)D2);
        float z = fmaf(m, Wd[0], bd[0]);
        out[node] = 1.0f / (1.0f + expf(-z));
    }
}

// ---------------------------------------------------------------------------
extern "C" void kernel_launch(void* const* d_in, const int* in_sizes, int n_in,
                              void* d_out, int out_size) {
    const float* x   = (const float*)d_in[0];
    const int*   src = (const int*)  d_in[1];
    const int*   dst = (const int*)  d_in[2];
    const float* W1  = (const float*)d_in[3];
    const float* b1  = (const float*)d_in[4];
    const float* W2  = (const float*)d_in[5];
    const float* b2  = (const float*)d_in[6];
    const float* Wd  = (const float*)d_in[7];
    const float* bd  = (const float*)d_in[8];
    float* out = (float*)d_out;

    const int N = in_sizes[0] / D1;
    const int E = in_sizes[1];

    __half *xh, *x2th;
    int *cnt, *row, *cur, *csr, *bsum;
    cudaGetSymbolAddress((void**)&xh,   g_xh);
    cudaGetSymbolAddress((void**)&x2th, g_x2th);
    cudaGetSymbolAddress((void**)&cnt,  g_cnt);
    cudaGetSymbolAddress((void**)&row,  g_row);
    cudaGetSymbolAddress((void**)&cur,  g_cur);
    cudaGetSymbolAddress((void**)&csr,  g_csr);
    cudaGetSymbolAddress((void**)&bsum, g_bsum);

    const int nb = (N + SCAN_B - 1) / SCAN_B;
    const int n4 = N * (D1 / 4);

    // --- CSR build + fp16 conversion (cnt zeroing folded into conv) ---
    conv_kernel<<<(n4 + 255) / 256, 256>>>(
        reinterpret_cast<const float4*>(x), reinterpret_cast<uint2*>(xh), cnt, n4, N);
    hist_kernel<<<(E + 255) / 256, 256>>>(dst, cnt, E);
    scan1_kernel<<<nb, SCAN_B>>>(cnt, row, bsum, N);
    scan23_kernel<<<nb, SCAN_B>>>(row, cur, bsum, N, E);
    fill_kernel<<<(E + 255) / 256, 256>>>(src, dst, cur, csr, E);

    // --- fused layers ---
    layer1_kernel<<<(N + 31) / 32, 256>>>(xh, csr, row, W1, b1, W2, x2th, N);
    layer2_kernel<<<(N + 63) / 64, 512>>>(x2th, csr, row, b2, Wd, bd, out, N);
}

// round 8
// speedup vs baseline: 2.5543x; 1.0225x over previous
#include <cuda_runtime.h>
#include <cuda_fp16.h>
#include <cstdint>
#include <math.h>

#define N_NODES_MAX 100000
#define E_MAX       1600000
#define D1 64
#define D2 32
#define SCAN_B 512
#define NB_MAX 256   // ceil(100000/512)=196

// Scratch (no allocations allowed)
__device__ __half g_xh  [(size_t)N_NODES_MAX * D1];  // fp16 copy of input features
__device__ __half g_x2th[(size_t)N_NODES_MAX * D2];  // fp16 (relu(agg@W1+b1))@W2
__device__ int    g_cnt [N_NODES_MAX];               // zeroed by scan (self-restoring)
__device__ int    g_row [N_NODES_MAX + 1];
__device__ int    g_cur [N_NODES_MAX];
__device__ int    g_csr [E_MAX];
__device__ int    g_agg [NB_MAX];                    // lookback publish slots (0 = empty)

// ---------------------------------------------------------------------------
// Packed f32x2 helpers (Blackwell FFMA2 — PTX-only).
__device__ __forceinline__ unsigned long long pack2r(float v) {
    unsigned long long r;
    asm("mov.b64 %0, {%1, %1};" : "=l"(r) : "r"(__float_as_uint(v)));
    return r;
}
__device__ __forceinline__ void unpack2(unsigned long long v, float& lo, float& hi) {
    unsigned int a, b;
    asm("mov.b64 {%0, %1}, %2;" : "=r"(a), "=r"(b) : "l"(v));
    lo = __uint_as_float(a);
    hi = __uint_as_float(b);
}
__device__ __forceinline__ unsigned long long fma2(unsigned long long a,
                                                   unsigned long long b,
                                                   unsigned long long c) {
    unsigned long long d;
    asm("fma.rn.f32x2 %0, %1, %2, %3;" : "=l"(d) : "l"(a), "l"(b), "l"(c));
    return d;
}

// ---------------------------------------------------------------------------
// conv (fp32->fp16) + degree histogram, merged. cnt was zeroed by the previous
// call's scan kernel (device globals zero-init covers the first call).
__global__ void conv_hist_kernel(const float4* __restrict__ x4,
                                 uint2* __restrict__ xh,
                                 const int* __restrict__ dst,
                                 int* __restrict__ cnt,
                                 int n4, int E) {
    int i = blockIdx.x * blockDim.x + threadIdx.x;
    if (i < n4) {
        float4 v = x4[i];
        __half2 a = __floats2half2_rn(v.x, v.y);
        __half2 b = __floats2half2_rn(v.z, v.w);
        uint2 o;
        o.x = *reinterpret_cast<unsigned int*>(&a);
        o.y = *reinterpret_cast<unsigned int*>(&b);
        xh[i] = o;
    }
    if (i < E) atomicAdd(&cnt[dst[i]], 1);
}

// ---------------------------------------------------------------------------
// Single-pass exclusive scan with decoupled lookback. 196 blocks (all
// co-resident; lower-indexed blocks never wait on higher ones, so no deadlock).
// Also zeroes cnt for the next call (read happens first, same thread).
__global__ void __launch_bounds__(SCAN_B)
scan_kernel(int* __restrict__ cnt, int* __restrict__ row, int* __restrict__ cur,
            int* __restrict__ agg, int N, int E) {
    __shared__ int s[SCAN_B];
    int t = threadIdx.x;
    int b = blockIdx.x;
    int i = b * SCAN_B + t;
    int v = (i < N) ? cnt[i] : 0;
    if (i < N) cnt[i] = 0;
    s[t] = v;
    __syncthreads();
#pragma unroll
    for (int off = 1; off < SCAN_B; off <<= 1) {
        int u = 0;
        if (t >= off) u = s[t - off];
        __syncthreads();
        if (t >= off) s[t] += u;
        __syncthreads();
    }
    int incl = s[t];
    // publish block aggregate (+1 so 0 means "not ready")
    if (t == 0) atomicExch(&agg[b], s[SCAN_B - 1] + 1);

    // lookback: cooperatively sum all predecessors' aggregates
    int acc = 0;
    for (int idx = t; idx < b; idx += SCAN_B) {
        volatile int* p = &agg[idx];
        int a;
        while ((a = *p) == 0) { }
        acc += a - 1;
    }
    __syncthreads();
    s[t] = acc;
    __syncthreads();
#pragma unroll
    for (int off = SCAN_B / 2; off > 0; off >>= 1) {
        if (t < off) s[t] += s[t + off];
        __syncthreads();
    }
    int offset = s[0];
    if (i < N) {
        int r = offset + incl - v;
        row[i] = r;
        cur[i] = r;
    }
    if (i == N) row[N] = E;
}

// ---------------------------------------------------------------------------
// CSR fill; also resets the lookback publish slots for the next call.
__global__ void fill_kernel(const int* __restrict__ src, const int* __restrict__ dst,
                            int* __restrict__ cur, int* __restrict__ csr,
                            int* __restrict__ agg, int E) {
    int i = blockIdx.x * blockDim.x + threadIdx.x;
    if (i < NB_MAX) agg[i] = 0;
    if (i < E) {
        int d = dst[i];
        int p = atomicAdd(&cur[d], 1);
        csr[p] = src[i];
    }
}

// ---------------------------------------------------------------------------
__device__ __forceinline__ void acc_h8(float* acc, uint4 v) {
    float2 f;
    f = __half22float2(*reinterpret_cast<__half2*>(&v.x)); acc[0] += f.x; acc[1] += f.y;
    f = __half22float2(*reinterpret_cast<__half2*>(&v.y)); acc[2] += f.x; acc[3] += f.y;
    f = __half22float2(*reinterpret_cast<__half2*>(&v.z)); acc[4] += f.x; acc[5] += f.y;
    f = __half22float2(*reinterpret_cast<__half2*>(&v.w)); acc[6] += f.x; acc[7] += f.y;
}

// Fused layer 1 + W2 pre-transform. Block = 256 threads, 32 nodes.
//   Phase A: fp16 gather mean, 8 lanes/node, 16B per lane.
//   Phase B: x1 = relu(agg@W1+b1); tile = 2 nodes x 4 outputs; FFMA2 packs
//            output-column pairs so W pairs load directly via LDS.128.
//   Phase C: x2t = x1@W2 (fp16 store), same packing.
#define L1_PAD 68
__global__ void __launch_bounds__(256, 6)
layer1_kernel(const __half* __restrict__ xh,
              const int*    __restrict__ csr,
              const int*    __restrict__ row,
              const float*  __restrict__ W1,   // [64,64] (k, j)
              const float*  __restrict__ b1,   // [64]
              const float*  __restrict__ W2,   // [64,32] (k, j)
              __half*       __restrict__ x2th, // [N,32] fp16
              int N) {
    __shared__ float W1s[D1 * D1];
    __shared__ float W2s[D1 * D2];
    __shared__ float b1s[D1];
    __shared__ float in_s[32][L1_PAD];

    for (int i = threadIdx.x; i < D1 * D1; i += blockDim.x) W1s[i] = W1[i];
    for (int i = threadIdx.x; i < D1 * D2; i += blockDim.x) W2s[i] = W2[i];
    if (threadIdx.x < D1) b1s[threadIdx.x] = b1[threadIdx.x];
    __syncthreads();

    // ---- Phase A: fp16 gather ----
    {
        int nl = threadIdx.x >> 3;
        int lane = threadIdx.x & 7;
        int node = blockIdx.x * 32 + nl;
        if (node >= N) node = N - 1;

        int beg = row[node], end = row[node + 1];
        const uint4* xh4 = reinterpret_cast<const uint4*>(xh);  // row stride 8

        float acc[8];
#pragma unroll
        for (int i = 0; i < 8; i++) acc[i] = 0.f;

        int e = beg;
        for (; e + 3 < end; e += 4) {
            int s0 = csr[e], s1 = csr[e + 1], s2 = csr[e + 2], s3 = csr[e + 3];
            uint4 v0 = xh4[(size_t)s0 * 8 + lane];
            uint4 v1 = xh4[(size_t)s1 * 8 + lane];
            uint4 v2 = xh4[(size_t)s2 * 8 + lane];
            uint4 v3 = xh4[(size_t)s3 * 8 + lane];
            acc_h8(acc, v0); acc_h8(acc, v1); acc_h8(acc, v2); acc_h8(acc, v3);
        }
        for (; e < end; e++) {
            uint4 v0 = xh4[(size_t)csr[e] * 8 + lane];
            acc_h8(acc, v0);
        }
        float inv = 1.0f / fmaxf((float)(end - beg), 1.0f);
        float4 r0 = make_float4(acc[0] * inv, acc[1] * inv, acc[2] * inv, acc[3] * inv);
        float4 r1 = make_float4(acc[4] * inv, acc[5] * inv, acc[6] * inv, acc[7] * inv);
        float4* rp = reinterpret_cast<float4*>(&in_s[nl][0]);
        rp[lane * 2]     = r0;
        rp[lane * 2 + 1] = r1;
    }
    __syncthreads();

    // ---- Phase B: x1 = relu(agg @ W1 + b1), FFMA2 over output-column pairs ----
    int j4 = threadIdx.x & 15;
    int np = threadIdx.x >> 4;
    int n0 = np * 2, n1 = n0 + 1;
    int j = j4 * 4;

    unsigned long long bj01 = *reinterpret_cast<const unsigned long long*>(&b1s[j]);
    unsigned long long bj23 = *reinterpret_cast<const unsigned long long*>(&b1s[j + 2]);
    unsigned long long oa01 = bj01, oa23 = bj23;   // node n0, outputs (j,j+1),(j+2,j+3)
    unsigned long long ob01 = bj01, ob23 = bj23;   // node n1
#pragma unroll
    for (int k = 0; k < D1; k += 4) {
        float4 xa4 = *reinterpret_cast<const float4*>(&in_s[n0][k]);
        float4 xb4 = *reinterpret_cast<const float4*>(&in_s[n1][k]);
#pragma unroll
        for (int kk = 0; kk < 4; kk++) {
            longlong2 ww = *reinterpret_cast<const longlong2*>(&W1s[(k + kk) * D1 + j]);
            float xa = (kk == 0) ? xa4.x : (kk == 1) ? xa4.y : (kk == 2) ? xa4.z : xa4.w;
            float xb = (kk == 0) ? xb4.x : (kk == 1) ? xb4.y : (kk == 2) ? xb4.z : xb4.w;
            unsigned long long xaa = pack2r(xa);
            unsigned long long xbb = pack2r(xb);
            oa01 = fma2(xaa, (unsigned long long)ww.x, oa01);
            oa23 = fma2(xaa, (unsigned long long)ww.y, oa23);
            ob01 = fma2(xbb, (unsigned long long)ww.x, ob01);
            ob23 = fma2(xbb, (unsigned long long)ww.y, ob23);
        }
    }
    float o00, o01, o02, o03, o10, o11, o12, o13;
    unpack2(oa01, o00, o01); unpack2(oa23, o02, o03);
    unpack2(ob01, o10, o11); unpack2(ob23, o12, o13);
    o00 = fmaxf(o00, 0.f); o01 = fmaxf(o01, 0.f);
    o02 = fmaxf(o02, 0.f); o03 = fmaxf(o03, 0.f);
    o10 = fmaxf(o10, 0.f); o11 = fmaxf(o11, 0.f);
    o12 = fmaxf(o12, 0.f); o13 = fmaxf(o13, 0.f);

    __syncthreads();
    in_s[n0][j + 0] = o00; in_s[n0][j + 1] = o01;
    in_s[n0][j + 2] = o02; in_s[n0][j + 3] = o03;
    in_s[n1][j + 0] = o10; in_s[n1][j + 1] = o11;
    in_s[n1][j + 2] = o12; in_s[n1][j + 3] = o13;
    __syncthreads();

    // ---- Phase C: x2t = x1 @ W2 (fp16 store), FFMA2 column pairs ----
    int j2 = (threadIdx.x & 15) * 2;
    unsigned long long pa = 0ull, pb = 0ull;
#pragma unroll
    for (int k = 0; k < D1; k += 4) {
        float4 xa4 = *reinterpret_cast<const float4*>(&in_s[n0][k]);
        float4 xb4 = *reinterpret_cast<const float4*>(&in_s[n1][k]);
#pragma unroll
        for (int kk = 0; kk < 4; kk++) {
            unsigned long long w =
                *reinterpret_cast<const unsigned long long*>(&W2s[(k + kk) * D2 + j2]);
            float xa = (kk == 0) ? xa4.x : (kk == 1) ? xa4.y : (kk == 2) ? xa4.z : xa4.w;
            float xb = (kk == 0) ? xb4.x : (kk == 1) ? xb4.y : (kk == 2) ? xb4.z : xb4.w;
            pa = fma2(pack2r(xa), w, pa);
            pb = fma2(pack2r(xb), w, pb);
        }
    }
    float p00, p01, p10, p11;
    unpack2(pa, p00, p01);
    unpack2(pb, p10, p11);

    int node0 = blockIdx.x * 32 + n0;
    int node1 = blockIdx.x * 32 + n1;
    if (node0 >= N) node0 = N - 1;
    if (node1 >= N) node1 = N - 1;
    *reinterpret_cast<__half2*>(x2th + (size_t)node0 * D2 + j2) = __floats2half2_rn(p00, p01);
    *reinterpret_cast<__half2*>(x2th + (size_t)node1 * D2 + j2) = __floats2half2_rn(p10, p11);
}

// ---------------------------------------------------------------------------
// Layer 2 + readout (fp16 gather): agg2 = mean(x2t[nb]); h = relu(agg2+b2);
// out = sigmoid(mean(h)*Wd + bd). 8 lanes per node, 8B per lane.
__global__ void __launch_bounds__(512)
layer2_kernel(const __half* __restrict__ x2th,  // [N,32] fp16
              const int*    __restrict__ csr,
              const int*    __restrict__ row,
              const float*  __restrict__ b2,
              const float*  __restrict__ Wd,
              const float*  __restrict__ bd,
              float*        __restrict__ out,   // [N]
              int N) {
    __shared__ float bs[D2];
    if (threadIdx.x < D2) bs[threadIdx.x] = b2[threadIdx.x];
    __syncthreads();

    int grp = threadIdx.x >> 3;
    int lane = threadIdx.x & 7;
    int node = blockIdx.x * 64 + grp;
    if (node >= N) node = N - 1;

    int beg = row[node], end = row[node + 1];
    const uint2* x2 = reinterpret_cast<const uint2*>(x2th);  // row stride 8

    float a0 = 0.f, a1 = 0.f, a2 = 0.f, a3 = 0.f;
    int e = beg;
    for (; e + 3 < end; e += 4) {
        int s0 = csr[e], s1 = csr[e + 1], s2 = csr[e + 2], s3 = csr[e + 3];
        uint2 v0 = x2[(size_t)s0 * 8 + lane];
        uint2 v1 = x2[(size_t)s1 * 8 + lane];
        uint2 v2 = x2[(size_t)s2 * 8 + lane];
        uint2 v3 = x2[(size_t)s3 * 8 + lane];
        float2 f;
        f = __half22float2(*reinterpret_cast<__half2*>(&v0.x)); a0 += f.x; a1 += f.y;
        f = __half22float2(*reinterpret_cast<__half2*>(&v0.y)); a2 += f.x; a3 += f.y;
        f = __half22float2(*reinterpret_cast<__half2*>(&v1.x)); a0 += f.x; a1 += f.y;
        f = __half22float2(*reinterpret_cast<__half2*>(&v1.y)); a2 += f.x; a3 += f.y;
        f = __half22float2(*reinterpret_cast<__half2*>(&v2.x)); a0 += f.x; a1 += f.y;
        f = __half22float2(*reinterpret_cast<__half2*>(&v2.y)); a2 += f.x; a3 += f.y;
        f = __half22float2(*reinterpret_cast<__half2*>(&v3.x)); a0 += f.x; a1 += f.y;
        f = __half22float2(*reinterpret_cast<__half2*>(&v3.y)); a2 += f.x; a3 += f.y;
    }
    for (; e < end; e++) {
        uint2 v0 = x2[(size_t)csr[e] * 8 + lane];
        float2 f;
        f = __half22float2(*reinterpret_cast<__half2*>(&v0.x)); a0 += f.x; a1 += f.y;
        f = __half22float2(*reinterpret_cast<__half2*>(&v0.y)); a2 += f.x; a3 += f.y;
    }
    float inv = 1.0f / fmaxf((float)(end - beg), 1.0f);
    int j = lane * 4;
    float h0 = fmaxf(fmaf(a0, inv, bs[j + 0]), 0.f);
    float h1 = fmaxf(fmaf(a1, inv, bs[j + 1]), 0.f);
    float h2 = fmaxf(fmaf(a2, inv, bs[j + 2]), 0.f);
    float h3 = fmaxf(fmaf(a3, inv, bs[j + 3]), 0.f);

    float v = (h0 + h1) + (h2 + h3);
#pragma unroll
    for (int off = 4; off > 0; off >>= 1)
        v += __shfl_down_sync(0xffffffffu, v, off, 8);

    if (lane == 0) {
        float m = v * (1.0f / (float)D2);
        float z = fmaf(m, Wd[0], bd[0]);
        out[node] = 1.0f / (1.0f + expf(-z));
    }
}

// ---------------------------------------------------------------------------
extern "C" void kernel_launch(void* const* d_in, const int* in_sizes, int n_in,
                              void* d_out, int out_size) {
    const float* x   = (const float*)d_in[0];
    const int*   src = (const int*)  d_in[1];
    const int*   dst = (const int*)  d_in[2];
    const float* W1  = (const float*)d_in[3];
    const float* b1  = (const float*)d_in[4];
    const float* W2  = (const float*)d_in[5];
    const float* b2  = (const float*)d_in[6];
    const float* Wd  = (const float*)d_in[7];
    const float* bd  = (const float*)d_in[8];
    float* out = (float*)d_out;

    const int N = in_sizes[0] / D1;
    const int E = in_sizes[1];

    __half *xh, *x2th;
    int *cnt, *row, *cur, *csr, *agg;
    cudaGetSymbolAddress((void**)&xh,   g_xh);
    cudaGetSymbolAddress((void**)&x2th, g_x2th);
    cudaGetSymbolAddress((void**)&cnt,  g_cnt);
    cudaGetSymbolAddress((void**)&row,  g_row);
    cudaGetSymbolAddress((void**)&cur,  g_cur);
    cudaGetSymbolAddress((void**)&csr,  g_csr);
    cudaGetSymbolAddress((void**)&agg,  g_agg);

    const int nb = (N + SCAN_B - 1) / SCAN_B;
    const int n4 = N * (D1 / 4);
    const int big = (n4 > E) ? n4 : E;

    // --- CSR build + fp16 conversion (5 launches total) ---
    conv_hist_kernel<<<(big + 255) / 256, 256>>>(
        reinterpret_cast<const float4*>(x), reinterpret_cast<uint2*>(xh),
        dst, cnt, n4, E);
    scan_kernel<<<nb, SCAN_B>>>(cnt, row, cur, agg, N, E);
    fill_kernel<<<(E + 255) / 256, 256>>>(src, dst, cur, csr, agg, E);

    // --- fused layers ---
    layer1_kernel<<<(N + 31) / 32, 256>>>(xh, csr, row, W1, b1, W2, x2th, N);
    layer2_kernel<<<(N + 63) / 64, 512>>>(x2th, csr, row, b2, Wd, bd, out, N);
}